// round 10
// baseline (speedup 1.0000x reference)
#include <cuda_runtime.h>
#include <cstdint>
#include <cstddef>

// HugeNet: 10000 x (Linear(100,100)+ReLU) scan, then Linear(100,10).
//
// Round 10: 384 threads (12 warps -> 3/SMSP, no spills), 64 CTAs x 4 rows.
// 6-way k-split, exact bases {0,20,36,52,68,84} (widths {20,16x5}).
// Thread (kq = w%6, m = (w/6)*32 + lane): cols (2m, 2m+1), 4 rows, k-group kq.
// W double-buffered in registers (10|8 float4), streamed from a
// thread-interleaved gmem layout with immediate-offset LDG.128.
// Reduction: red[kq][jj*4+r][m] smem; phase2 = 200 threads x 2 cols.

#define N_LAYERS 10000
#define D        100
#define D_OUT    10
#define NCTA     64
#define THREADS  384
#define NKQ      6
#define LSLOTS   50                      // 2 * 25 quads
#define LF4      (LSLOTS * 64)           // 3200 float4 per layer
#define LBYTES   (LF4 * 16)              // 51200 B per layer

typedef unsigned long long ull;

// [(N_LAYERS+2)][50][64] float4  (~512MB, zero-padded)
__device__ __align__(16) float4 g_Wp[(size_t)(N_LAYERS + 2) * LF4];

__host__ __device__ __forceinline__ int kqb(int kq) {           // k base
    return kq ? (20 + 16 * (kq - 1)) : 0;   // {0,20,36,52,68,84}
}
__host__ __device__ __forceinline__ int kqn(int kq) {           // quads
    return kq ? 4 : 5;
}
__host__ __device__ __forceinline__ int kqoff(int kq) {         // quad prefix
    return kq ? (5 + 4 * (kq - 1)) : 0;     // {0,5,9,13,17,21}
}

// ---------------------------------------------------------------------------
// prep: W[l][j][k] row-major -> g_Wp[l*3200 + slot*64 + m]
//   slot = (kqoff(kq)+q)*2 + jj;  j = 2m+jj;  k = kqb(kq)+4q
// ---------------------------------------------------------------------------
__global__ void prep_kernel(const float* __restrict__ W) {
    size_t idx = (size_t)blockIdx.x * blockDim.x + threadIdx.x;
    const size_t total = (size_t)(N_LAYERS + 2) * LF4;
    if (idx >= total) return;
    int    m    = (int)(idx & 63);
    size_t rest = idx >> 6;
    int    slot = (int)(rest % LSLOTS);
    size_t l    = rest / LSLOTS;
    int kq, local;
    if (slot < 10) { kq = 0; local = slot; }
    else           { kq = 1 + (slot - 10) / 8; local = (slot - 10) % 8; }
    int q  = local >> 1;
    int jj = local & 1;
    int j  = 2 * m + jj;
    int k  = kqb(kq) + 4 * q;
    float4 v = make_float4(0.f, 0.f, 0.f, 0.f);
    if (l < N_LAYERS && j < D)
        v = *reinterpret_cast<const float4*>(
                W + l * (size_t)(D * D) + (size_t)j * D + k);
    g_Wp[idx] = v;
}

// ---------------------------------------------------------------------------
__device__ __forceinline__ void fma2(ull& a, ull x, ull y) {
    asm("fma.rn.f32x2 %0, %1, %2, %0;" : "+l"(a) : "l"(x), "l"(y));
}
__device__ __forceinline__ float2 upk(ull v) {
    float2 r;
    asm("mov.b64 {%0, %1}, %2;" : "=f"(r.x), "=f"(r.y) : "l"(v));
    return r;
}

__global__ void __launch_bounds__(THREADS, 1)
hugenet_kernel(const float* __restrict__ x,
               const float* __restrict__ bg,
               const float* __restrict__ Wo,
               const float* __restrict__ bo,
               float* __restrict__ out) {
    __shared__ float h[2][4][104];        // 3.3KB
    __shared__ float red[NKQ][8][64];     // 12KB

    const int tid  = threadIdx.x;
    const int lane = tid & 31, w = tid >> 5;
    const int kq   = w % NKQ;
    const int m    = (w / NKQ) * 32 + lane;
    const bool live = (m < 50);
    const int kb   = kqb(kq);
    const int r0   = blockIdx.x * 4;

    // phase-2 role: 200 threads, (row r2, col pair jp)
    const bool p2live = (tid < 200);
    const int  r2 = tid / 50, jp = tid % 50;

    for (int idx = tid; idx < 4 * D; idx += THREADS)
        h[0][idx / D][idx % D] = x[(size_t)(r0 + idx / D) * D + idx % D];
    __syncthreads();

    float4 Wa[10], Wb[10];
    float2 pba = make_float2(0.f, 0.f), pbb = pba;

    // per-thread W base: layer base + (kqoff*2)*1024 + m*16
    const char* wptr = reinterpret_cast<const char*>(g_Wp)
                     + (size_t)(kqoff(kq) * 2) * 1024 + (size_t)m * 16;

    auto ldW = [&](float4* R, size_t l) {
        if (!live) return;
        const char* p = wptr + l * (size_t)LBYTES;
        if (kq == 0) {
            #pragma unroll
            for (int i = 0; i < 10; i++)
                R[i] = __ldg(reinterpret_cast<const float4*>(p + i * 1024));
        } else {
            #pragma unroll
            for (int i = 0; i < 8; i++)
                R[i] = __ldg(reinterpret_cast<const float4*>(p + i * 1024));
        }
    };
    auto ldPB = [&](float2& bb, int l) {
        if (p2live && l < N_LAYERS)
            bb = *reinterpret_cast<const float2*>(bg + (size_t)l * D + 2 * jp);
    };

    auto phase1 = [&](const float4* R, int HB) {
        if (live) {
            ull a[8] = {0,0,0,0,0,0,0,0};
            const int NQ = (kq == 0) ? 5 : 4;   // warp-uniform
            #pragma unroll 5
            for (int q = 0; q < NQ; q++) {
                ulonglong2 w0 = *reinterpret_cast<const ulonglong2*>(&R[2*q]);
                ulonglong2 w1 = *reinterpret_cast<const ulonglong2*>(&R[2*q+1]);
                #pragma unroll
                for (int r = 0; r < 4; r++) {
                    ulonglong2 hv = *reinterpret_cast<const ulonglong2*>(
                                        &h[HB][r][kb + 4 * q]);
                    fma2(a[r],     hv.x, w0.x);
                    fma2(a[r],     hv.y, w0.y);
                    fma2(a[4 + r], hv.x, w1.x);
                    fma2(a[4 + r], hv.y, w1.y);
                }
            }
            #pragma unroll
            for (int i = 0; i < 8; i++) {
                float2 u = upk(a[i]);
                red[kq][i][m] = u.x + u.y;
            }
        }
    };

    auto phase2 = [&](float2 pb, int HB) {
        if (p2live) {
            float s0 = pb.x, s1 = pb.y;
            #pragma unroll
            for (int g = 0; g < NKQ; g++) s0 += red[g][r2][jp];
            #pragma unroll
            for (int g = 0; g < NKQ; g++) s1 += red[g][4 + r2][jp];
            *reinterpret_cast<float2*>(&h[HB ^ 1][r2][2 * jp]) =
                make_float2(fmaxf(s0, 0.f), fmaxf(s1, 0.f));
        }
    };

    ldW(Wa, 0);  ldW(Wb, 1);
    ldPB(pba, 0); ldPB(pbb, 1);

    #pragma unroll 1
    for (int l = 0; l < N_LAYERS; l += 2) {
        // layer l: h[0] -> h[1]
        phase1(Wa, 0);
        float2 pb0 = pba;
        ldW(Wa, (size_t)l + 2); ldPB(pba, l + 2);
        __syncthreads();
        phase2(pb0, 0);
        __syncthreads();

        // layer l+1: h[1] -> h[0]
        phase1(Wb, 1);
        float2 pb1 = pbb;
        ldW(Wb, (size_t)l + 3); ldPB(pbb, l + 3);
        __syncthreads();
        phase2(pb1, 1);
        __syncthreads();
    }

    // Final Linear(100, 10). h in h[0].
    if (tid < 4 * D_OUT) {
        int r = tid / D_OUT, o = tid % D_OUT;
        const float* hr = h[0][r];
        float acc = bo[o];
        #pragma unroll
        for (int k = 0; k < D; k++)
            acc += hr[k] * __ldg(&Wo[(size_t)o * D + k]);
        out[(size_t)(r0 + r) * D_OUT + o] = acc;
    }
}

// ---------------------------------------------------------------------------
extern "C" void kernel_launch(void* const* d_in, const int* in_sizes, int n_in,
                              void* d_out, int out_size) {
    const float *x = nullptr, *W = nullptr, *b = nullptr, *Wo = nullptr, *bo = nullptr;
    for (int i = 0; i < n_in; i++) {
        switch (in_sizes[i]) {
            case 25600:     x  = (const float*)d_in[i]; break;
            case 100000000: W  = (const float*)d_in[i]; break;
            case 1000000:   b  = (const float*)d_in[i]; break;
            case 1000:      Wo = (const float*)d_in[i]; break;
            case 10:        bo = (const float*)d_in[i]; break;
            default: break;
        }
    }

    const size_t total = (size_t)(N_LAYERS + 2) * LF4;
    int blocks = (int)((total + 255) / 256);
    prep_kernel<<<blocks, 256>>>(W);

    hugenet_kernel<<<NCTA, THREADS>>>(x, b, Wo, bo, (float*)d_out);
}

// round 12
// speedup vs baseline: 1.3301x; 1.3301x over previous
#include <cuda_runtime.h>
#include <cstdint>
#include <cstddef>

// HugeNet: 10000 x (Linear(100,100)+ReLU) scan, then Linear(100,10).
//
// Round 12: int16 fixed-point W (scale 2^18), R11 design with the scale
// constant FIXED (R11 used 2^-15 for SC against SCI=2^18 -> gain 8/layer
// -> divergence). SC = 2^-18 exactly.
// Skeleton = R3 (best known): 64 CTAs x 4 rows, 256 threads,
// kq = tid>>6 (k-groups {0:28,28:52,52:76,76:100}), m = tid&63 (col pair),
// smem partial reduction, phase2 on tid<50, two barriers/layer.

#define N_LAYERS 10000
#define D        100
#define D_OUT    10
#define NCTA     64
#define THREADS  256
#define QS       7                       // max quads per thread (kq0)
#define LSTRIDE  (QS * THREADS)          // uint4 per layer = 1792
#define SC       3.814697265625e-06f    // 2^-18  (== 1/SCI)
#define SCI      262144.0f              // 2^18

typedef unsigned long long ull;

// [(N_LAYERS+2)][7][256] uint4 of s16x8 (~287MB, zero-padded)
__device__ __align__(16) uint4 g_Wq[(size_t)(N_LAYERS + 2) * LSTRIDE];
// bias * 2^-18
__device__ float g_bp[(size_t)N_LAYERS * D];

__host__ __device__ __forceinline__ int kqb(int kq) {
    return kq ? (28 + 24 * (kq - 1)) : 0;   // {0,28,52,76}
}
__host__ __device__ __forceinline__ int kqn(int kq) {
    return kq ? 6 : 7;                      // exact: 28+24+24+24 = 100
}

// ---------------------------------------------------------------------------
// prep W: slot(l, q, t) -> uint4 of 8 s16:
//   t: m = t&63, kq = t>>6; cols j0=2m, j1=2m+1; k = kqb(kq)+4q .. +3
//   .x = j0 k0,k1 | .y = j0 k2,k3 | .z = j1 k0,k1 | .w = j1 k2,k3
// ---------------------------------------------------------------------------
__device__ __forceinline__ unsigned pack2(const float* W, size_t l,
                                          int j, int k) {
    float w0 = W[l * (size_t)(D * D) + (size_t)j * D + k];
    float w1 = W[l * (size_t)(D * D) + (size_t)j * D + k + 1];
    int q0 = __float2int_rn(w0 * SCI);     // |w| < 0.1 -> |q| <= 26215
    int q1 = __float2int_rn(w1 * SCI);
    return (unsigned)(unsigned short)(short)q0 |
           ((unsigned)(unsigned short)(short)q1 << 16);
}

__global__ void prep_w(const float* __restrict__ W) {
    size_t idx = (size_t)blockIdx.x * blockDim.x + threadIdx.x;
    const size_t total = (size_t)(N_LAYERS + 2) * LSTRIDE;
    if (idx >= total) return;
    int    t    = (int)(idx & (THREADS - 1));
    size_t rest = idx >> 8;
    int    q    = (int)(rest % QS);
    size_t l    = rest / QS;
    int m = t & 63, kq = t >> 6;
    int j0 = 2 * m, k = kqb(kq) + 4 * q;
    uint4 v = make_uint4(0u, 0u, 0u, 0u);
    if (l < N_LAYERS && j0 + 1 < D && q < kqn(kq)) {
        v.x = pack2(W, l, j0,     k);
        v.y = pack2(W, l, j0,     k + 2);
        v.z = pack2(W, l, j0 + 1, k);
        v.w = pack2(W, l, j0 + 1, k + 2);
    }
    g_Wq[idx] = v;
}

__global__ void prep_b(const float* __restrict__ b) {
    size_t idx = (size_t)blockIdx.x * blockDim.x + threadIdx.x;
    if (idx < (size_t)N_LAYERS * D) g_bp[idx] = b[idx] * SC;
}

// ---------------------------------------------------------------------------
__device__ __forceinline__ void fma2(ull& a, ull x, ull y) {
    asm("fma.rn.f32x2 %0, %1, %2, %0;" : "+l"(a) : "l"(x), "l"(y));
}
__device__ __forceinline__ float2 upk(ull v) {
    float2 r;
    asm("mov.b64 {%0, %1}, %2;" : "=f"(r.x), "=f"(r.y) : "l"(v));
    return r;
}
// s16x2 (packed in u32) -> fp32x2 (packed in u64), exact integer values
__device__ __forceinline__ ull cvt2(unsigned v) {
    ull r;
    asm("{ .reg .b16 lo, hi; .reg .f32 f0, f1;\n"
        "  mov.b32 {lo, hi}, %1;\n"
        "  cvt.rn.f32.s16 f0, lo;\n"
        "  cvt.rn.f32.s16 f1, hi;\n"
        "  mov.b64 %0, {f0, f1}; }" : "=l"(r) : "r"(v));
    return r;
}

// templated quad loop: NQ known at compile time (7 or 6)
template <int NQ>
__device__ __forceinline__ void quads(const uint4* R, const float* hk,
                                      ull* a) {
    #pragma unroll
    for (int q = 0; q < NQ; q++) {
        uint4 wq = R[q];
        ull w00 = cvt2(wq.x), w01 = cvt2(wq.y);
        ull w10 = cvt2(wq.z), w11 = cvt2(wq.w);
        #pragma unroll
        for (int r = 0; r < 4; r++) {
            ulonglong2 hv =
                *reinterpret_cast<const ulonglong2*>(hk + r * 104 + 4 * q);
            fma2(a[r],     hv.x, w00);
            fma2(a[r],     hv.y, w01);
            fma2(a[4 + r], hv.x, w10);
            fma2(a[4 + r], hv.y, w11);
        }
    }
}

__global__ void __launch_bounds__(THREADS, 1)
hugenet_kernel(const float* __restrict__ x,
               const float* __restrict__ Wo,
               const float* __restrict__ bo,
               float* __restrict__ out) {
    __shared__ float h[2][4][104];        // stores h2 = h * 2^-18
    __shared__ float red[3][8][64];       // partials from kq=1..3

    const int tid = threadIdx.x;
    const int m   = tid & 63;
    const int kq  = tid >> 6;
    const int kb  = kqb(kq);
    const bool live = (m < 50);
    const int r0  = blockIdx.x * 4;

    for (int idx = tid; idx < 4 * D; idx += THREADS)
        h[0][idx / D][idx % D] = x[(size_t)(r0 + idx / D) * D + idx % D] * SC;
    __syncthreads();

    uint4 Wa[QS], Wb[QS];
    #pragma unroll
    for (int i = 0; i < QS; i++) { Wa[i] = make_uint4(0,0,0,0); Wb[i] = Wa[i]; }
    float2 pba = make_float2(0.f, 0.f), pbb = pba;

    auto ldW = [&](uint4* R, size_t l) {
        if (!live) return;
        const uint4* p = g_Wq + l * LSTRIDE + tid;
        if (kq == 0) {
            #pragma unroll
            for (int i = 0; i < 7; i++) R[i] = __ldg(p + i * THREADS);
        } else {
            #pragma unroll
            for (int i = 0; i < 6; i++) R[i] = __ldg(p + i * THREADS);
        }
    };
    auto ldB = [&](float2& bb, int l) {
        if (tid < 50 && l < N_LAYERS)
            bb = *reinterpret_cast<const float2*>(g_bp + (size_t)l * D + 2 * tid);
    };

    auto do_layer = [&](const uint4* R, float2 bias, int HB) {
        ull a[8] = {0ull,0ull,0ull,0ull,0ull,0ull,0ull,0ull};
        const float* hk = &h[HB][0][0] + kb;
        if (kq == 0) quads<7>(R, hk, a);
        else         quads<6>(R, hk, a);

        float p[8];
        #pragma unroll
        for (int i = 0; i < 8; i++) {
            float2 u = upk(a[i]);
            p[i] = u.x + u.y;
        }
        if (kq) {
            #pragma unroll
            for (int i = 0; i < 8; i++) red[kq - 1][i][m] = p[i];
        }
        __syncthreads();

        if (tid < 50) {
            float v[8];
            #pragma unroll
            for (int i = 0; i < 8; i++) {
                // s = exact pre-activation (h2*2^18 dot w); v = h2_next
                float s = p[i] + red[0][i][m] + red[1][i][m] + red[2][i][m];
                float bp = (i < 4) ? bias.x : bias.y;
                v[i] = fmaxf(fmaf(s, SC, bp), 0.f);
            }
            #pragma unroll
            for (int r = 0; r < 4; r++)
                *reinterpret_cast<float2*>(&h[HB ^ 1][r][2 * m]) =
                    make_float2(v[r], v[4 + r]);
        }
        __syncthreads();
    };

    ldW(Wa, 0);
    ldB(pba, 0);

    #pragma unroll 1
    for (int l = 0; l < N_LAYERS; l += 2) {
        ldW(Wb, l + 1);
        ldB(pbb, l + 1);

        do_layer(Wa, pba, 0);             // h[0] -> h[1]

        ldW(Wa, (size_t)l + 2);           // pad layers zeroed
        ldB(pba, l + 2);

        do_layer(Wb, pbb, 1);             // h[1] -> h[0]
    }

    // Final Linear(100, 10): h2 in h[0]; out = 2^18 * (h2 @ Wo^T) + bo
    if (tid < 4 * D_OUT) {
        int r = tid / D_OUT, o = tid % D_OUT;
        const float* hr = h[0][r];
        float acc = 0.f;
        #pragma unroll
        for (int k = 0; k < D; k++)
            acc += hr[k] * __ldg(&Wo[(size_t)o * D + k]);
        out[(size_t)(r0 + r) * D_OUT + o] = fmaf(acc, SCI, bo[o]);
    }
}

// ---------------------------------------------------------------------------
extern "C" void kernel_launch(void* const* d_in, const int* in_sizes, int n_in,
                              void* d_out, int out_size) {
    const float *x = nullptr, *W = nullptr, *b = nullptr, *Wo = nullptr, *bo = nullptr;
    for (int i = 0; i < n_in; i++) {
        switch (in_sizes[i]) {
            case 25600:     x  = (const float*)d_in[i]; break;
            case 100000000: W  = (const float*)d_in[i]; break;
            case 1000000:   b  = (const float*)d_in[i]; break;
            case 1000:      Wo = (const float*)d_in[i]; break;
            case 10:        bo = (const float*)d_in[i]; break;
            default: break;
        }
    }

    const size_t totalW = (size_t)(N_LAYERS + 2) * LSTRIDE;
    prep_w<<<(int)((totalW + 255) / 256), 256>>>(W);
    const size_t totalB = (size_t)N_LAYERS * D;
    prep_b<<<(int)((totalB + 255) / 256), 256>>>(b);

    hugenet_kernel<<<NCTA, THREADS>>>(x, Wo, bo, (float*)d_out);
}

// round 13
// speedup vs baseline: 1.6701x; 1.2557x over previous
#include <cuda_runtime.h>
#include <cstdint>
#include <cstddef>

// HugeNet: 10000 x (Linear(100,100)+ReLU) scan, then Linear(100,10).
//
// Round 13: clean 512-thread experiment (4 warps/SMSP, guaranteed no
// spill: ~100 regs/thread). J=1 col/thread, 4-way k-split.
//   kq = tid>>7 (k-groups {0:28,28:52,52:76,76:100}), j = tid&127 (<100 live)
// W double-buffered in registers (7|6 float4), streamed from
// thread-interleaved fp32 gmem layout. smem reduction red[4][128][4]
// (STS.128 / LDS.128, conflict-free), parallel phase2 on 100 threads.
// 64 CTAs x 4 rows, 2 barriers/layer, pure fp32 math.

#define N_LAYERS 10000
#define D        100
#define D_OUT    10
#define NCTA     64
#define THREADS  512
#define QS       7                          // max quads/thread (kq0)
#define LSTRIDE  (QS * THREADS)             // float4 per layer = 3584

typedef unsigned long long ull;

// [(N_LAYERS+2)][7][512] float4 (~573MB, zero-padded)
__device__ __align__(16) float4 g_Wp[(size_t)(N_LAYERS + 2) * LSTRIDE];

__host__ __device__ __forceinline__ int kqb(int kq) {
    return kq ? (28 + 24 * (kq - 1)) : 0;   // {0,28,52,76}
}
__host__ __device__ __forceinline__ int kqn(int kq) {
    return kq ? 6 : 7;                      // widths {28,24,24,24} = 100
}

// ---------------------------------------------------------------------------
// prep: W[l][j][k] row-major -> g_Wp[(l*QS + q)*512 + t]
//   t: kq = t>>7, j = t&127;  k = kqb(kq) + 4q
// ---------------------------------------------------------------------------
__global__ void prep_kernel(const float* __restrict__ W) {
    size_t idx = (size_t)blockIdx.x * blockDim.x + threadIdx.x;
    const size_t total = (size_t)(N_LAYERS + 2) * LSTRIDE;
    if (idx >= total) return;
    int    t    = (int)(idx & (THREADS - 1));
    size_t rest = idx >> 9;
    int    q    = (int)(rest % QS);
    size_t l    = rest / QS;
    int kq = t >> 7, j = t & 127;
    int k  = kqb(kq) + 4 * q;
    float4 v = make_float4(0.f, 0.f, 0.f, 0.f);
    if (l < N_LAYERS && j < D && q < kqn(kq))
        v = *reinterpret_cast<const float4*>(
                W + l * (size_t)(D * D) + (size_t)j * D + k);
    g_Wp[idx] = v;
}

// ---------------------------------------------------------------------------
__device__ __forceinline__ void fma2(ull& a, ull x, ull y) {
    asm("fma.rn.f32x2 %0, %1, %2, %0;" : "+l"(a) : "l"(x), "l"(y));
}
__device__ __forceinline__ float2 upk(ull v) {
    float2 r;
    asm("mov.b64 {%0, %1}, %2;" : "=f"(r.x), "=f"(r.y) : "l"(v));
    return r;
}

__global__ void __launch_bounds__(THREADS, 1)
hugenet_kernel(const float* __restrict__ x,
               const float* __restrict__ bg,
               const float* __restrict__ Wo,
               const float* __restrict__ bo,
               float* __restrict__ out) {
    __shared__ float h[2][4][104];          // 3.3KB
    __shared__ float red[4][128][4];        // 8KB; [kq][j][r]

    const int tid = threadIdx.x;
    const int kq  = tid >> 7;               // warp-uniform (warps 0-3: kq0,...)
    const int j   = tid & 127;
    const int kb  = kqb(kq);
    const int nq  = kqn(kq);
    const bool live = (j < D);
    const int r0  = blockIdx.x * 4;

    for (int idx = tid; idx < 4 * D; idx += THREADS)
        h[0][idx / D][idx % D] = x[(size_t)(r0 + idx / D) * D + idx % D];
    __syncthreads();

    float4 Wa[QS], Wb[QS];
    float  ba = 0.f, bb = 0.f;

    auto ldW = [&](float4* R, size_t l) {
        const float4* p = g_Wp + l * LSTRIDE + tid;
        if (kq == 0) {
            #pragma unroll
            for (int i = 0; i < 7; i++) R[i] = __ldg(p + i * THREADS);
        } else {
            #pragma unroll
            for (int i = 0; i < 6; i++) R[i] = __ldg(p + i * THREADS);
        }
    };
    auto ldB = [&](float& b, int l) {
        if (tid < D && l < N_LAYERS) b = __ldg(bg + (size_t)l * D + tid);
    };

    auto do_layer = [&](const float4* R, float bias, int HB) {
        // phase 1: partial dot for column j over this thread's k-group
        ull a[4] = {0ull, 0ull, 0ull, 0ull};
        if (kq == 0) {
            #pragma unroll
            for (int q = 0; q < 7; q++) {
                ulonglong2 w = *reinterpret_cast<const ulonglong2*>(&R[q]);
                #pragma unroll
                for (int r = 0; r < 4; r++) {
                    ulonglong2 hv = *reinterpret_cast<const ulonglong2*>(
                                        &h[HB][r][kb + 4 * q]);
                    fma2(a[r], hv.x, w.x);
                    fma2(a[r], hv.y, w.y);
                }
            }
        } else {
            #pragma unroll
            for (int q = 0; q < 6; q++) {
                ulonglong2 w = *reinterpret_cast<const ulonglong2*>(&R[q]);
                #pragma unroll
                for (int r = 0; r < 4; r++) {
                    ulonglong2 hv = *reinterpret_cast<const ulonglong2*>(
                                        &h[HB][r][kb + 4 * q]);
                    fma2(a[r], hv.x, w.x);
                    fma2(a[r], hv.y, w.y);
                }
            }
        }
        float4 p;
        {
            float2 u0 = upk(a[0]), u1 = upk(a[1]),
                   u2 = upk(a[2]), u3 = upk(a[3]);
            p = make_float4(u0.x + u0.y, u1.x + u1.y,
                            u2.x + u2.y, u3.x + u3.y);
        }
        *reinterpret_cast<float4*>(&red[kq][j][0]) = p;   // STS.128
        __syncthreads();

        // phase 2: 100 threads, column j2 = tid, all 4 rows
        if (tid < D) {
            float4 s0 = *reinterpret_cast<const float4*>(&red[0][tid][0]);
            float4 s1 = *reinterpret_cast<const float4*>(&red[1][tid][0]);
            float4 s2 = *reinterpret_cast<const float4*>(&red[2][tid][0]);
            float4 s3 = *reinterpret_cast<const float4*>(&red[3][tid][0]);
            float v0 = fmaxf((s0.x + s1.x) + (s2.x + s3.x) + bias, 0.f);
            float v1 = fmaxf((s0.y + s1.y) + (s2.y + s3.y) + bias, 0.f);
            float v2 = fmaxf((s0.z + s1.z) + (s2.z + s3.z) + bias, 0.f);
            float v3 = fmaxf((s0.w + s1.w) + (s2.w + s3.w) + bias, 0.f);
            h[HB ^ 1][0][tid] = v0;
            h[HB ^ 1][1][tid] = v1;
            h[HB ^ 1][2][tid] = v2;
            h[HB ^ 1][3][tid] = v3;
        }
        __syncthreads();
    };

    ldW(Wa, 0);
    ldB(ba, 0);

    #pragma unroll 1
    for (int l = 0; l < N_LAYERS; l += 2) {
        ldW(Wb, (size_t)l + 1);
        ldB(bb, l + 1);

        do_layer(Wa, ba, 0);                // h[0] -> h[1]

        ldW(Wa, (size_t)l + 2);             // pad layers zeroed
        ldB(ba, l + 2);

        do_layer(Wb, bb, 1);                // h[1] -> h[0]
    }

    // Final Linear(100, 10): 40 threads. h in h[0].
    if (tid < 4 * D_OUT) {
        int r = tid / D_OUT, o = tid % D_OUT;
        const float* hr = h[0][r];
        float acc = bo[o];
        #pragma unroll
        for (int k = 0; k < D; k++)
            acc += hr[k] * __ldg(&Wo[(size_t)o * D + k]);
        out[(size_t)(r0 + r) * D_OUT + o] = acc;
    }
}

// ---------------------------------------------------------------------------
extern "C" void kernel_launch(void* const* d_in, const int* in_sizes, int n_in,
                              void* d_out, int out_size) {
    const float *x = nullptr, *W = nullptr, *b = nullptr, *Wo = nullptr, *bo = nullptr;
    for (int i = 0; i < n_in; i++) {
        switch (in_sizes[i]) {
            case 25600:     x  = (const float*)d_in[i]; break;
            case 100000000: W  = (const float*)d_in[i]; break;
            case 1000000:   b  = (const float*)d_in[i]; break;
            case 1000:      Wo = (const float*)d_in[i]; break;
            case 10:        bo = (const float*)d_in[i]; break;
            default: break;
        }
    }

    const size_t total = (size_t)(N_LAYERS + 2) * LSTRIDE;
    prep_kernel<<<(int)((total + 255) / 256), 256>>>(W);

    hugenet_kernel<<<NCTA, THREADS>>>(x, b, Wo, bo, (float*)d_out);
}